// round 8
// baseline (speedup 1.0000x reference)
#include <cuda_runtime.h>
#include <cuda_fp16.h>
#include <cstdint>

// Problem sizes
static constexpr int NL = 2048;
static constexpr int NU = 6144;
static constexpr int NT = 8192;   // NL + NU
static constexpr int D  = 512;
static constexpr int CC = 1000;

// Scratch (device globals; no allocation allowed)
__device__ __half g_nh[(size_t)NT * D];      // normalized feats fp16 (8MB)
__device__ float  g_cv[(size_t)NT * CC];     // class_val fp32 (rows >= NL used)
__device__ __half g_cvT[(size_t)1024 * NT];  // class_val^T fp16 (cols >= NL used)
__device__ __half g_E[(size_t)NT * NT];      // exp(S) fp16 (134MB)
__device__ float  g_rsum[NT];                // softmax denominators (atomic-accumulated)
__device__ int    g_label[NL];               // argmax of lb_one_hot rows

// ============================================================================
// Helpers
// ============================================================================
__device__ __forceinline__ uint32_t smem_u32(const void* p) {
    uint32_t a;
    asm("{ .reg .u64 t; cvta.to.shared.u64 t, %1; cvt.u32.u64 %0, t; }" : "=r"(a) : "l"(p));
    return a;
}
// swizzled byte offset inside a tile of 128B rows (8 x 16B segments per row)
__device__ __forceinline__ uint32_t smoff(int row, int seg) {
    return (uint32_t)(row * 128 + ((seg ^ (row & 7)) << 4));
}
#define CP16(dst, src) \
    asm volatile("cp.async.cg.shared.global [%0], [%1], 16;" :: "r"(dst), "l"(src) : "memory")
#define CP_COMMIT() asm volatile("cp.async.commit_group;" ::: "memory")
#define CP_WAIT1() asm volatile("cp.async.wait_group 1;" ::: "memory")

__device__ __forceinline__ void ldm_x4(uint32_t* r, uint32_t addr) {
    asm volatile("ldmatrix.sync.aligned.m8n8.x4.shared.b16 {%0,%1,%2,%3}, [%4];"
                 : "=r"(r[0]), "=r"(r[1]), "=r"(r[2]), "=r"(r[3]) : "r"(addr));
}
__device__ __forceinline__ void mma16816(float* d, const uint32_t* a, const uint32_t* b) {
    asm volatile(
        "mma.sync.aligned.m16n8k16.row.col.f32.f16.f16.f32 "
        "{%0,%1,%2,%3}, {%4,%5,%6,%7}, {%8,%9}, {%0,%1,%2,%3};"
        : "+f"(d[0]), "+f"(d[1]), "+f"(d[2]), "+f"(d[3])
        : "r"(a[0]), "r"(a[1]), "r"(a[2]), "r"(a[3]), "r"(b[0]), "r"(b[1]));
}

// FMA-only exp, valid for |x| <= ~11, rel err < 2e-7
__device__ __forceinline__ float fast_expf(float x) {
    float z = x * 1.4426950408889634f;
    float n = rintf(z);
    float r = fmaf(n, -0.6931471824645996f, x);
    r = fmaf(n, 1.9046542743e-9f, r);
    float p = 1.3888889225e-3f;
    p = fmaf(p, r, 8.3333337680e-3f);
    p = fmaf(p, r, 4.1666667908e-2f);
    p = fmaf(p, r, 1.6666667163e-1f);
    p = fmaf(p, r, 5.0e-1f);
    p = fmaf(p, r, 1.0f);
    p = fmaf(p, r, 1.0f);
    float s = __int_as_float(((int)n + 127) << 23);
    return p * s;
}

__device__ __forceinline__ float blockMax256(float v) {
    __shared__ float s[8];
    #pragma unroll
    for (int o = 16; o > 0; o >>= 1) v = fmaxf(v, __shfl_xor_sync(0xffffffffu, v, o));
    if ((threadIdx.x & 31) == 0) s[threadIdx.x >> 5] = v;
    __syncthreads();
    float r = s[0];
    #pragma unroll
    for (int i = 1; i < 8; i++) r = fmaxf(r, s[i]);
    __syncthreads();
    return r;
}
__device__ __forceinline__ float blockSum256(float v) {
    __shared__ float s[8];
    #pragma unroll
    for (int o = 16; o > 0; o >>= 1) v += __shfl_xor_sync(0xffffffffu, v, o);
    if ((threadIdx.x & 31) == 0) s[threadIdx.x >> 5] = v;
    __syncthreads();
    float r = s[0];
    #pragma unroll
    for (int i = 1; i < 8; i++) r += s[i];
    __syncthreads();
    return r;
}

// ============================================================================
// Kernel 1: L2-normalize concat(lb_feat, anchor) -> fp16
// ============================================================================
__global__ void normalize_kernel(const float* __restrict__ lb_feat,
                                 const float* __restrict__ anchor) {
    const int row = blockIdx.x;
    const int t = threadIdx.x;
    const float* src = (row < NL) ? lb_feat + (size_t)row * D
                                  : anchor + (size_t)(row - NL) * D;
    float4 v = ((const float4*)src)[t];
    float ss = v.x * v.x + v.y * v.y + v.z * v.z + v.w * v.w;
    #pragma unroll
    for (int o = 16; o > 0; o >>= 1) ss += __shfl_xor_sync(0xffffffffu, ss, o);
    __shared__ float ws[4];
    if ((t & 31) == 0) ws[t >> 5] = ss;
    __syncthreads();
    float tot = ws[0] + ws[1] + ws[2] + ws[3];
    float sc = 1.0f / fmaxf(sqrtf(tot), 1e-12f);
    __half2 hA = __floats2half2_rn(v.x * sc, v.y * sc);
    __half2 hB = __floats2half2_rn(v.z * sc, v.w * sc);
    uint2 hp;
    hp.x = *(uint32_t*)&hA; hp.y = *(uint32_t*)&hB;
    ((uint2*)(g_nh + (size_t)row * D))[t] = hp;
}

// ============================================================================
// Kernel 2: rows < NL: extract label (argmax of one-hot).
//           rows >= NL: softmax(logits_x_ulb_1) -> g_cv.
// ============================================================================
__global__ void classval_kernel(const float* __restrict__ lb_one_hot,
                                const float* __restrict__ logits) {
    const int row = blockIdx.x;
    const int t = threadIdx.x;
    if (row < NL) {
        const float* src = lb_one_hot + (size_t)row * CC;
        #pragma unroll
        for (int q = 0; q < 4; q++) {
            int c = t + q * 256;
            if (c < CC && src[c] > 0.5f) g_label[row] = c;
        }
        return;
    }
    const float* src = logits + (size_t)(row - NL) * CC;
    float* dst = g_cv + (size_t)row * CC;
    float v[4];
    float mx = -1e30f;
    #pragma unroll
    for (int q = 0; q < 4; q++) {
        int j = t + q * 256;
        v[q] = (j < CC) ? src[j] : -1e30f;
        mx = fmaxf(mx, v[q]);
    }
    mx = blockMax256(mx);
    float sum = 0.f;
    #pragma unroll
    for (int q = 0; q < 4; q++) {
        int j = t + q * 256;
        float e = (j < CC) ? fast_expf(v[q] - mx) : 0.f;
        v[q] = e;
        sum += e;
    }
    sum = blockSum256(sum);
    float inv = 1.0f / sum;
    #pragma unroll
    for (int q = 0; q < 4; q++) {
        int j = t + q * 256;
        if (j < CC) dst[j] = v[q] * inv;
    }
}

// ============================================================================
// Kernel 3: transpose g_cv rows [NL,NT) fp32 -> g_cvT[c][k] fp16 (k >= NL)
// ============================================================================
__global__ void transpose_cv_kernel() {
    __shared__ float s[32][33];
    const int k0 = NL + blockIdx.x * 32, c0 = blockIdx.y * 32;
    const int tx = threadIdx.x & 31, ty = threadIdx.x >> 5;
    #pragma unroll
    for (int q = 0; q < 4; q++) {
        int k = k0 + ty + q * 8, c = c0 + tx;
        s[ty + q * 8][tx] = (c < CC) ? g_cv[(size_t)k * CC + c] : 0.f;
    }
    __syncthreads();
    #pragma unroll
    for (int q = 0; q < 4; q++) {
        int c = c0 + ty + q * 8, k = k0 + tx;
        g_cvT[(size_t)c * NT + k] = __float2half_rn(s[tx][ty + q * 8]);
    }
}

// ============================================================================
// Kernel 4: GEMM1 (HMMA): dot = n@n^T (single-pass fp16); E = exp(10*dot)
// SYMMETRIC: upper-triangular 128x128 blocks; off-diagonal blocks also write
// the transposed tile (staged through SMEM). Fused rowsums via atomics.
// kc=64, 3-stage cp.async (32KB/stage = 96KB), 2 CTA/SM, ONE sync per chunk.
// ============================================================================
__device__ __forceinline__ void g1_load(uint32_t sb, int s, int c, int i0, int j0, int t) {
    #pragma unroll
    for (int q = 0; q < 4; q++) {
        int u = t + q * 256, row = u >> 3, seg = u & 7;
        uint32_t so = smoff(row, seg);
        uint32_t dA = sb + s * 32768 + so;
        size_t ga = ((size_t)(i0 + row) * D + c * 64 + seg * 8) * 2;
        size_t gb = ((size_t)(j0 + row) * D + c * 64 + seg * 8) * 2;
        CP16(dA,         (const char*)g_nh + ga);
        CP16(dA + 16384, (const char*)g_nh + gb);
    }
}

static constexpr int NB = NT / 128;  // 64 blocks per dim
static constexpr int TP = 136;       // transpose-stage pitch in halves

__global__ __launch_bounds__(256, 2) void gemm1_kernel() {
    extern __shared__ char smem[];
    const uint32_t sb = smem_u32(smem);
    const int t = threadIdx.x, lane = t & 31, w = t >> 5;
    const int wm = w >> 2, wn = w & 3;

    // triangular decode: blockIdx.x -> (bi, bj), bi <= bj
    int bi = 0, rem = blockIdx.x;
    while (rem >= NB - bi) { rem -= NB - bi; bi++; }
    const int bj = bi + rem;
    const int i0 = bi * 128, j0 = bj * 128;

    float acc[4][4][4];
    #pragma unroll
    for (int a = 0; a < 4; a++)
        #pragma unroll
        for (int b = 0; b < 4; b++)
            #pragma unroll
            for (int cth = 0; cth < 4; cth++) acc[a][b][cth] = 0.f;

    const int rA = wm * 64 + (lane & 15);
    const int sA = lane >> 4;
    const int rB = wn * 32 + ((lane >> 4) & 1) * 8 + (lane & 7);
    const int sB = (lane >> 3) & 1;

    g1_load(sb, 0, 0, i0, j0, t); CP_COMMIT();
    g1_load(sb, 1, 1, i0, j0, t); CP_COMMIT();

    constexpr int NCH = D / 64;  // 8 chunks
    for (int c = 0; c < NCH; c++) {
        const int st = c % 3;
        CP_WAIT1();        // retire chunk c's group (c+1 may stay in flight)
        __syncthreads();   // c visible to all; all reads of stage (c-1)%3 done
        if (c + 2 < NCH) g1_load(sb, (c + 2) % 3, c + 2, i0, j0, t);
        CP_COMMIT();       // always commit (possibly empty) to keep accounting
        const uint32_t bA = sb + st * 32768;
        const uint32_t bB = bA + 16384;
        #pragma unroll
        for (int kk = 0; kk < 4; kk++) {
            uint32_t af[4][4], bf[8];
            #pragma unroll
            for (int mt = 0; mt < 4; mt++)
                ldm_x4(af[mt], bA + smoff(rA + mt * 16, 2 * kk + sA));
            #pragma unroll
            for (int jj = 0; jj < 2; jj++)
                ldm_x4(bf + jj * 4, bB + smoff(rB + jj * 16, 2 * kk + sB));
            #pragma unroll
            for (int mt = 0; mt < 4; mt++)
                #pragma unroll
                for (int nt = 0; nt < 4; nt++)
                    mma16816(acc[mt][nt], af[mt], bf + nt * 2);
        }
    }
    __syncthreads();   // all stage reads done; smem reusable for staging

    // Epilogue: E = exp(10*acc) -> fp16; fused row sums.
    const int g = lane >> 2, cq = lane & 3;
    __half* sT = (__half*)smem;  // pitch TP halves
    #pragma unroll
    for (int mt = 0; mt < 4; mt++) {
        #pragma unroll
        for (int h = 0; h < 2; h++) {
            const int rl = wm * 64 + mt * 16 + g + h * 8;      // local row
            __half* erow = g_E + (size_t)(i0 + rl) * NT + j0 + wn * 32;
            float rs = 0.f;
            #pragma unroll
            for (int nt = 0; nt < 4; nt++) {
                float e0 = fast_expf(acc[mt][nt][2 * h] * 10.f);
                float e1 = fast_expf(acc[mt][nt][2 * h + 1] * 10.f);
                __half2 p = __floats2half2_rn(e0, e1);
                *(__half2*)(erow + nt * 8 + cq * 2) = p;
                float2 pf = __half22float2(p);   // sum the rounded values
                rs += pf.x + pf.y;
                if (bi != bj) {
                    const int cl = wn * 32 + nt * 8 + cq * 2;
                    sT[(size_t)cl * TP + rl]       = __low2half(p);
                    sT[(size_t)(cl + 1) * TP + rl] = __high2half(p);
                }
            }
            // reduce across the 4 cq lanes sharing this row
            rs += __shfl_xor_sync(0xffffffffu, rs, 1);
            rs += __shfl_xor_sync(0xffffffffu, rs, 2);
            if (cq == 0) atomicAdd(&g_rsum[i0 + rl], rs);
        }
    }
    if (bi != bj) {
        __syncthreads();
        // coalesced write of transposed tile + its row sums (= column sums)
        #pragma unroll
        for (int q = 0; q < 8; q++) {
            int u = t + q * 256;
            int row = u >> 4, seg = u & 15;  // seg == lane & 15
            uint4 v = *(const uint4*)(sT + row * TP + seg * 8);
            *(uint4*)(g_E + (size_t)(j0 + row) * NT + i0 + seg * 8) = v;
            const __half2* hh = (const __half2*)&v;
            float s = 0.f;
            #pragma unroll
            for (int k = 0; k < 4; k++) {
                float2 f = __half22float2(hh[k]);
                s += f.x + f.y;
            }
            s += __shfl_xor_sync(0xffffffffu, s, 1);
            s += __shfl_xor_sync(0xffffffffu, s, 2);
            s += __shfl_xor_sync(0xffffffffu, s, 4);
            s += __shfl_xor_sync(0xffffffffu, s, 8);
            if (seg == 0) atomicAdd(&g_rsum[j0 + row], s);
        }
    }
}

// ============================================================================
// Kernel 5: GEMM2 (HMMA): out = (E[:,2048:] @ cvT[:,2048:]^T) / rsum
// Block 128x256, warp tile 64x64 (2x4 warps), 1 CTA/SM. K = 6144, kc=64.
// Stage = A 16KB | B 32KB = 48KB; 3 stages = 144KB. ONE sync per chunk.
// Rationale (R7 post-mortem): smem-port bandwidth was the wall; 64x64 warp
// tiles cut LDS bytes/flop by 31% and halve E re-reads (4 j-blocks not 8).
// ============================================================================
__device__ __forceinline__ void g2_load(uint32_t sb, int s, int c, int i0, int j0, int t) {
    const uint32_t base = sb + s * 49152;
    #pragma unroll
    for (int q = 0; q < 4; q++) {   // A: 128 rows x 128B
        int u = t + q * 256, row = u >> 3, seg = u & 7;
        CP16(base + smoff(row, seg),
             (const char*)g_E + ((size_t)(i0 + row) * NT + NL + c * 64 + seg * 8) * 2);
    }
    #pragma unroll
    for (int q = 0; q < 8; q++) {   // B: 256 rows x 128B
        int u = t + q * 256, row = u >> 3, seg = u & 7;
        CP16(base + 16384 + smoff(row, seg),
             (const char*)g_cvT + ((size_t)(j0 + row) * NT + NL + c * 64 + seg * 8) * 2);
    }
}

__global__ __launch_bounds__(256, 1) void gemm2_kernel(float* __restrict__ out) {
    extern __shared__ char smem[];
    const uint32_t sb = smem_u32(smem);
    const int t = threadIdx.x, lane = t & 31, w = t >> 5;
    const int wm = w >> 2, wn = w & 3;           // 2 x 4 warp grid
    const int i0 = blockIdx.y * 128, j0 = blockIdx.x * 256;

    float acc[4][8][4];                           // 64 x 64 warp tile
    #pragma unroll
    for (int a = 0; a < 4; a++)
        #pragma unroll
        for (int b = 0; b < 8; b++)
            #pragma unroll
            for (int cth = 0; cth < 4; cth++) acc[a][b][cth] = 0.f;

    const int rA = wm * 64 + (lane & 15);
    const int sA = lane >> 4;
    const int rB = wn * 64 + ((lane >> 4) & 1) * 8 + (lane & 7);
    const int sB = (lane >> 3) & 1;

    g2_load(sb, 0, 0, i0, j0, t); CP_COMMIT();
    g2_load(sb, 1, 1, i0, j0, t); CP_COMMIT();

    constexpr int NCH = (NT - NL) / 64;  // 96
    for (int c = 0; c < NCH; c++) {
        const int st = c % 3;
        CP_WAIT1();
        __syncthreads();
        if (c + 2 < NCH) g2_load(sb, (c + 2) % 3, c + 2, i0, j0, t);
        CP_COMMIT();
        const uint32_t bA = sb + st * 49152;
        const uint32_t bB = bA + 16384;
        #pragma unroll
        for (int kk = 0; kk < 4; kk++) {
            uint32_t af[4][4], bf[4][4];
            #pragma unroll
            for (int mt = 0; mt < 4; mt++)
                ldm_x4(af[mt], bA + smoff(rA + mt * 16, 2 * kk + sA));
            #pragma unroll
            for (int jj = 0; jj < 4; jj++)
                ldm_x4(bf[jj], bB + smoff(rB + jj * 16, 2 * kk + sB));
            #pragma unroll
            for (int mt = 0; mt < 4; mt++)
                #pragma unroll
                for (int nt = 0; nt < 8; nt++)
                    mma16816(acc[mt][nt], af[mt], &bf[nt >> 1][(nt & 1) * 2]);
        }
    }

    const int g = lane >> 2, cq = lane & 3;
    #pragma unroll
    for (int mt = 0; mt < 4; mt++) {
        #pragma unroll
        for (int h = 0; h < 2; h++) {
            const int row = i0 + wm * 64 + mt * 16 + g + h * 8;
            const float inv = 1.0f / g_rsum[row];
            float* crow = out + (size_t)row * CC;
            #pragma unroll
            for (int nt = 0; nt < 8; nt++) {
                int col = j0 + wn * 64 + nt * 8 + cq * 2;
                if (col < CC) {
                    float2 v = make_float2(acc[mt][nt][2 * h] * inv,
                                           acc[mt][nt][2 * h + 1] * inv);
                    *(float2*)(crow + col) = v;
                }
            }
        }
    }
}

// ============================================================================
// Kernel 6: scatter the labeled (one-hot) K-range into out.
// out[i][c] += (sum_{j<NL, label[j]==c} E[i][j]) / rsum[i]
// ============================================================================
__global__ __launch_bounds__(256) void scatter_kernel(float* __restrict__ out) {
    __shared__ float accum[CC];
    __shared__ int lab[NL];
    const int i = blockIdx.x, t = threadIdx.x;
    #pragma unroll
    for (int q = 0; q < 4; q++) {
        int c = t + q * 256;
        if (c < CC) accum[c] = 0.f;
    }
    #pragma unroll
    for (int q = 0; q < 8; q++) lab[t + q * 256] = g_label[t + q * 256];
    __syncthreads();
    uint4 u = ((const uint4*)(g_E + (size_t)i * NT))[t];
    const __half2* h = (const __half2*)&u;
    const int j0 = t * 8;
    #pragma unroll
    for (int k = 0; k < 4; k++) {
        float2 f = __half22float2(h[k]);
        atomicAdd(&accum[lab[j0 + 2 * k]],     f.x);
        atomicAdd(&accum[lab[j0 + 2 * k + 1]], f.y);
    }
    __syncthreads();
    const float inv = 1.0f / g_rsum[i];
    float* crow = out + (size_t)i * CC;
    #pragma unroll
    for (int q = 0; q < 4; q++) {
        int c = t + q * 256;
        if (c < CC) crow[c] += accum[c] * inv;
    }
}

// ============================================================================
// Launch. Output layout (float32):
//   [0)         anchor_feat    3145728
//   [3145728)   positive_feat  3145728
//   [6291456)   lb_feat        1048576
//   [7340032)   lb_one_hot     2048000
//   [9388032)   new_lb||new_ulb1  8192000 (contiguous 8192x1000)
//   [17580032)  logits_x_ulb_2 6144000
// ============================================================================
extern "C" void kernel_launch(void* const* d_in, const int* in_sizes, int n_in,
                              void* d_out, int out_size) {
    const float* anchor   = (const float*)d_in[0];
    const float* positive = (const float*)d_in[1];
    const float* lb_feat  = (const float*)d_in[2];
    const float* lb_oh    = (const float*)d_in[3];
    const float* lg_ulb1  = (const float*)d_in[5];
    const float* lg_ulb2  = (const float*)d_in[6];
    float* out = (float*)d_out;

    cudaMemcpyAsync(out,            anchor,   (size_t)NU * D  * sizeof(float), cudaMemcpyDeviceToDevice, 0);
    cudaMemcpyAsync(out + 3145728,  positive, (size_t)NU * D  * sizeof(float), cudaMemcpyDeviceToDevice, 0);
    cudaMemcpyAsync(out + 6291456,  lb_feat,  (size_t)NL * D  * sizeof(float), cudaMemcpyDeviceToDevice, 0);
    cudaMemcpyAsync(out + 7340032,  lb_oh,    (size_t)NL * CC * sizeof(float), cudaMemcpyDeviceToDevice, 0);
    cudaMemcpyAsync(out + 17580032, lg_ulb2,  (size_t)NU * CC * sizeof(float), cudaMemcpyDeviceToDevice, 0);

    void* rsum_ptr = nullptr;
    cudaGetSymbolAddress(&rsum_ptr, g_rsum);
    cudaMemsetAsync(rsum_ptr, 0, NT * sizeof(float), 0);

    normalize_kernel<<<NT, 128>>>(lb_feat, anchor);
    classval_kernel<<<NT, 256>>>(lb_oh, lg_ulb1);
    transpose_cv_kernel<<<dim3((NT - NL) / 32, 1024 / 32), 256>>>();

    cudaFuncSetAttribute(gemm1_kernel, cudaFuncAttributeMaxDynamicSharedMemorySize, 98304);
    cudaFuncSetAttribute(gemm2_kernel, cudaFuncAttributeMaxDynamicSharedMemorySize, 147456);

    gemm1_kernel<<<NB * (NB + 1) / 2, 256, 98304>>>();   // 2080 triangular blocks
    gemm2_kernel<<<dim3(4, 64), 256, 147456>>>(out + 9388032);
    scatter_kernel<<<NT, 256>>>(out + 9388032);
}

// round 9
// speedup vs baseline: 1.0431x; 1.0431x over previous
#include <cuda_runtime.h>
#include <cuda_fp16.h>
#include <cstdint>

// Problem sizes
static constexpr int NL = 2048;
static constexpr int NU = 6144;
static constexpr int NT = 8192;   // NL + NU
static constexpr int D  = 512;
static constexpr int CC = 1000;

// Scratch (device globals; no allocation allowed)
__device__ __half g_nh[(size_t)NT * D];      // normalized feats fp16 (8MB)
__device__ float  g_cv[(size_t)NT * CC];     // class_val fp32 (rows >= NL used)
__device__ __half g_cvT[(size_t)1024 * NT];  // class_val^T fp16 (cols >= NL used)
__device__ __half g_E[(size_t)NT * NT];      // exp(S) fp16 (134MB)
__device__ float  g_rsum[NT];                // softmax denominators (atomic-accumulated)
__device__ int    g_label[NL];               // argmax of lb_one_hot rows

// ============================================================================
// Helpers
// ============================================================================
__device__ __forceinline__ uint32_t smem_u32(const void* p) {
    uint32_t a;
    asm("{ .reg .u64 t; cvta.to.shared.u64 t, %1; cvt.u32.u64 %0, t; }" : "=r"(a) : "l"(p));
    return a;
}
// swizzled byte offset inside a tile of 128B rows (8 x 16B segments per row)
__device__ __forceinline__ uint32_t smoff(int row, int seg) {
    return (uint32_t)(row * 128 + ((seg ^ (row & 7)) << 4));
}
#define CP16(dst, src) \
    asm volatile("cp.async.cg.shared.global [%0], [%1], 16;" :: "r"(dst), "l"(src) : "memory")
#define CP_COMMIT() asm volatile("cp.async.commit_group;" ::: "memory")
#define CP_WAIT1() asm volatile("cp.async.wait_group 1;" ::: "memory")

__device__ __forceinline__ void ldm_x4(uint32_t* r, uint32_t addr) {
    asm volatile("ldmatrix.sync.aligned.m8n8.x4.shared.b16 {%0,%1,%2,%3}, [%4];"
                 : "=r"(r[0]), "=r"(r[1]), "=r"(r[2]), "=r"(r[3]) : "r"(addr));
}
__device__ __forceinline__ void mma16816(float* d, const uint32_t* a, const uint32_t* b) {
    asm volatile(
        "mma.sync.aligned.m16n8k16.row.col.f32.f16.f16.f32 "
        "{%0,%1,%2,%3}, {%4,%5,%6,%7}, {%8,%9}, {%0,%1,%2,%3};"
        : "+f"(d[0]), "+f"(d[1]), "+f"(d[2]), "+f"(d[3])
        : "r"(a[0]), "r"(a[1]), "r"(a[2]), "r"(a[3]), "r"(b[0]), "r"(b[1]));
}

// FMA-only exp, valid for |x| <= ~11, rel err < 2e-7
__device__ __forceinline__ float fast_expf(float x) {
    float z = x * 1.4426950408889634f;
    float n = rintf(z);
    float r = fmaf(n, -0.6931471824645996f, x);
    r = fmaf(n, 1.9046542743e-9f, r);
    float p = 1.3888889225e-3f;
    p = fmaf(p, r, 8.3333337680e-3f);
    p = fmaf(p, r, 4.1666667908e-2f);
    p = fmaf(p, r, 1.6666667163e-1f);
    p = fmaf(p, r, 5.0e-1f);
    p = fmaf(p, r, 1.0f);
    p = fmaf(p, r, 1.0f);
    float s = __int_as_float(((int)n + 127) << 23);
    return p * s;
}

__device__ __forceinline__ float blockMax256(float v) {
    __shared__ float s[8];
    #pragma unroll
    for (int o = 16; o > 0; o >>= 1) v = fmaxf(v, __shfl_xor_sync(0xffffffffu, v, o));
    if ((threadIdx.x & 31) == 0) s[threadIdx.x >> 5] = v;
    __syncthreads();
    float r = s[0];
    #pragma unroll
    for (int i = 1; i < 8; i++) r = fmaxf(r, s[i]);
    __syncthreads();
    return r;
}
__device__ __forceinline__ float blockSum256(float v) {
    __shared__ float s[8];
    #pragma unroll
    for (int o = 16; o > 0; o >>= 1) v += __shfl_xor_sync(0xffffffffu, v, o);
    if ((threadIdx.x & 31) == 0) s[threadIdx.x >> 5] = v;
    __syncthreads();
    float r = s[0];
    #pragma unroll
    for (int i = 1; i < 8; i++) r += s[i];
    __syncthreads();
    return r;
}

// ============================================================================
// Kernel 1 (fused prep): per row:
//   - L2-normalize concat(lb_feat, anchor) -> g_nh (fp16), zero g_rsum
//   - row < NL: extract label; row >= NL: softmax(logits) -> g_cv
// ============================================================================
__global__ void prep_kernel(const float* __restrict__ lb_feat,
                            const float* __restrict__ anchor,
                            const float* __restrict__ lb_one_hot,
                            const float* __restrict__ logits) {
    const int row = blockIdx.x;
    const int t = threadIdx.x;
    // --- normalize (2 floats per thread) ---
    const float* srcn = (row < NL) ? lb_feat + (size_t)row * D
                                   : anchor + (size_t)(row - NL) * D;
    float2 v2 = ((const float2*)srcn)[t];
    float tot = blockSum256(v2.x * v2.x + v2.y * v2.y);
    float sc = 1.0f / fmaxf(sqrtf(tot), 1e-12f);
    __half2 hn = __floats2half2_rn(v2.x * sc, v2.y * sc);
    ((__half2*)(g_nh + (size_t)row * D))[t] = hn;
    if (t == 0) g_rsum[row] = 0.f;
    // --- class values / labels ---
    if (row < NL) {
        const float* src = lb_one_hot + (size_t)row * CC;
        #pragma unroll
        for (int q = 0; q < 4; q++) {
            int c = t + q * 256;
            if (c < CC && src[c] > 0.5f) g_label[row] = c;
        }
        return;
    }
    const float* src = logits + (size_t)(row - NL) * CC;
    float* dst = g_cv + (size_t)row * CC;
    float v[4];
    float mx = -1e30f;
    #pragma unroll
    for (int q = 0; q < 4; q++) {
        int j = t + q * 256;
        v[q] = (j < CC) ? src[j] : -1e30f;
        mx = fmaxf(mx, v[q]);
    }
    mx = blockMax256(mx);
    float sum = 0.f;
    #pragma unroll
    for (int q = 0; q < 4; q++) {
        int j = t + q * 256;
        float e = (j < CC) ? fast_expf(v[q] - mx) : 0.f;
        v[q] = e;
        sum += e;
    }
    sum = blockSum256(sum);
    float inv = 1.0f / sum;
    #pragma unroll
    for (int q = 0; q < 4; q++) {
        int j = t + q * 256;
        if (j < CC) dst[j] = v[q] * inv;
    }
}

// ============================================================================
// Kernel 2: transpose g_cv rows [NL,NT) fp32 -> g_cvT[c][k] fp16 (k >= NL)
// ============================================================================
__global__ void transpose_cv_kernel() {
    __shared__ float s[32][33];
    const int k0 = NL + blockIdx.x * 32, c0 = blockIdx.y * 32;
    const int tx = threadIdx.x & 31, ty = threadIdx.x >> 5;
    #pragma unroll
    for (int q = 0; q < 4; q++) {
        int k = k0 + ty + q * 8, c = c0 + tx;
        s[ty + q * 8][tx] = (c < CC) ? g_cv[(size_t)k * CC + c] : 0.f;
    }
    __syncthreads();
    #pragma unroll
    for (int q = 0; q < 4; q++) {
        int c = c0 + ty + q * 8, k = k0 + tx;
        g_cvT[(size_t)c * NT + k] = __float2half_rn(s[tx][ty + q * 8]);
    }
}

// ============================================================================
// Kernel 3: GEMM1 (HMMA): dot = n@n^T (fp16); E = exp(10*dot), fused rowsums.
// SYMMETRIC triangular 128x128 blocks; off-diag also writes transposed tile.
// 4 warps (2x2), 64x64 warp tiles, 2 CTA/SM, kc=64, 3-stage (96KB).
// Rationale (R8 post-mortem): 64x64 tiles cut LDSM redundancy to 2x/2x while
// 128-thread CTAs keep 2 CTAs/SM for bubble hiding -> tensor pipe binds.
// ============================================================================
__device__ __forceinline__ void g1_load(uint32_t sb, int s, int c, int i0, int j0, int t) {
    const uint32_t base = sb + s * 32768;
    #pragma unroll
    for (int q = 0; q < 8; q++) {
        int u = t + q * 128, row = u >> 3, seg = u & 7;
        uint32_t so = smoff(row, seg);
        size_t ga = ((size_t)(i0 + row) * D + c * 64 + seg * 8) * 2;
        size_t gb = ((size_t)(j0 + row) * D + c * 64 + seg * 8) * 2;
        CP16(base + so,         (const char*)g_nh + ga);
        CP16(base + 16384 + so, (const char*)g_nh + gb);
    }
}

static constexpr int NB = NT / 128;  // 64 blocks per dim
static constexpr int TP = 136;       // transpose-stage pitch in halves

__global__ __launch_bounds__(128, 2) void gemm1_kernel() {
    extern __shared__ char smem[];
    const uint32_t sb = smem_u32(smem);
    const int t = threadIdx.x, lane = t & 31, w = t >> 5;
    const int wm = w >> 1, wn = w & 1;           // 2 x 2 warp grid

    // triangular decode: blockIdx.x -> (bi, bj), bi <= bj
    int bi = 0, rem = blockIdx.x;
    while (rem >= NB - bi) { rem -= NB - bi; bi++; }
    const int bj = bi + rem;
    const int i0 = bi * 128, j0 = bj * 128;

    float acc[4][8][4];                           // 64 x 64 warp tile
    #pragma unroll
    for (int a = 0; a < 4; a++)
        #pragma unroll
        for (int b = 0; b < 8; b++)
            #pragma unroll
            for (int cth = 0; cth < 4; cth++) acc[a][b][cth] = 0.f;

    const int rA = wm * 64 + (lane & 15);
    const int sA = lane >> 4;
    const int rB = wn * 64 + ((lane >> 4) & 1) * 8 + (lane & 7);
    const int sB = (lane >> 3) & 1;

    g1_load(sb, 0, 0, i0, j0, t); CP_COMMIT();
    g1_load(sb, 1, 1, i0, j0, t); CP_COMMIT();

    constexpr int NCH = D / 64;  // 8 chunks
    for (int c = 0; c < NCH; c++) {
        const int st = c % 3;
        CP_WAIT1();        // retire chunk c's group
        __syncthreads();   // c visible; all reads of stage (c-1)%3 done
        if (c + 2 < NCH) g1_load(sb, (c + 2) % 3, c + 2, i0, j0, t);
        CP_COMMIT();       // always commit to keep accounting
        const uint32_t bA = sb + st * 32768;
        const uint32_t bB = bA + 16384;
        #pragma unroll
        for (int kk = 0; kk < 4; kk++) {
            uint32_t af[4][4], bf[4][4];
            #pragma unroll
            for (int mt = 0; mt < 4; mt++)
                ldm_x4(af[mt], bA + smoff(rA + mt * 16, 2 * kk + sA));
            #pragma unroll
            for (int jj = 0; jj < 4; jj++)
                ldm_x4(bf[jj], bB + smoff(rB + jj * 16, 2 * kk + sB));
            #pragma unroll
            for (int mt = 0; mt < 4; mt++)
                #pragma unroll
                for (int nt = 0; nt < 8; nt++)
                    mma16816(acc[mt][nt], af[mt], &bf[nt >> 1][(nt & 1) * 2]);
        }
    }
    __syncthreads();   // all stage reads done; smem reusable for staging

    // Epilogue: E = exp(10*acc) -> fp16; fused row sums.
    const int g = lane >> 2, cq = lane & 3;
    __half* sT = (__half*)smem;  // pitch TP halves
    #pragma unroll
    for (int mt = 0; mt < 4; mt++) {
        #pragma unroll
        for (int h = 0; h < 2; h++) {
            const int rl = wm * 64 + mt * 16 + g + h * 8;      // local row
            __half* erow = g_E + (size_t)(i0 + rl) * NT + j0 + wn * 64;
            float rs = 0.f;
            #pragma unroll
            for (int nt = 0; nt < 8; nt++) {
                float e0 = fast_expf(acc[mt][nt][2 * h] * 10.f);
                float e1 = fast_expf(acc[mt][nt][2 * h + 1] * 10.f);
                __half2 p = __floats2half2_rn(e0, e1);
                *(__half2*)(erow + nt * 8 + cq * 2) = p;
                float2 pf = __half22float2(p);   // sum the rounded values
                rs += pf.x + pf.y;
                if (bi != bj) {
                    const int cl = wn * 64 + nt * 8 + cq * 2;
                    sT[(size_t)cl * TP + rl]       = __low2half(p);
                    sT[(size_t)(cl + 1) * TP + rl] = __high2half(p);
                }
            }
            // reduce across the 4 cq lanes sharing this row (2 warps/row -> atomics)
            rs += __shfl_xor_sync(0xffffffffu, rs, 1);
            rs += __shfl_xor_sync(0xffffffffu, rs, 2);
            if (cq == 0) atomicAdd(&g_rsum[i0 + rl], rs);
        }
    }
    if (bi != bj) {
        __syncthreads();
        // coalesced write of transposed tile + its row sums (= column sums)
        #pragma unroll
        for (int q = 0; q < 16; q++) {
            int u = t + q * 128;
            int row = u >> 4, seg = u & 15;  // seg == t & 15 (128 % 16 == 0)
            uint4 v = *(const uint4*)(sT + row * TP + seg * 8);
            *(uint4*)(g_E + (size_t)(j0 + row) * NT + i0 + seg * 8) = v;
            const __half2* hh = (const __half2*)&v;
            float s = 0.f;
            #pragma unroll
            for (int k = 0; k < 4; k++) {
                float2 f = __half22float2(hh[k]);
                s += f.x + f.y;
            }
            s += __shfl_xor_sync(0xffffffffu, s, 1);
            s += __shfl_xor_sync(0xffffffffu, s, 2);
            s += __shfl_xor_sync(0xffffffffu, s, 4);
            s += __shfl_xor_sync(0xffffffffu, s, 8);
            if (seg == 0) atomicAdd(&g_rsum[j0 + row], s);
        }
    }
}

// ============================================================================
// Kernel 4: GEMM2 (HMMA): out = (E[:,2048:] @ cvT[:,2048:]^T) / rsum
// Block 128x128, 4 warps (2x2), 64x64 warp tiles, 2 CTA/SM. K=6144, kc=64,
// 3-stage (96KB). Same redundancy/occupancy rationale as gemm1.
// ============================================================================
__device__ __forceinline__ void g2_load(uint32_t sb, int s, int c, int i0, int j0, int t) {
    const uint32_t base = sb + s * 32768;
    #pragma unroll
    for (int q = 0; q < 8; q++) {
        int u = t + q * 128, row = u >> 3, seg = u & 7;
        uint32_t so = smoff(row, seg);
        CP16(base + so,
             (const char*)g_E + ((size_t)(i0 + row) * NT + NL + c * 64 + seg * 8) * 2);
        CP16(base + 16384 + so,
             (const char*)g_cvT + ((size_t)(j0 + row) * NT + NL + c * 64 + seg * 8) * 2);
    }
}

__global__ __launch_bounds__(128, 2) void gemm2_kernel(float* __restrict__ out) {
    extern __shared__ char smem[];
    const uint32_t sb = smem_u32(smem);
    const int t = threadIdx.x, lane = t & 31, w = t >> 5;
    const int wm = w >> 1, wn = w & 1;           // 2 x 2 warp grid
    const int i0 = blockIdx.y * 128, j0 = blockIdx.x * 128;

    float acc[4][8][4];                           // 64 x 64 warp tile
    #pragma unroll
    for (int a = 0; a < 4; a++)
        #pragma unroll
        for (int b = 0; b < 8; b++)
            #pragma unroll
            for (int cth = 0; cth < 4; cth++) acc[a][b][cth] = 0.f;

    const int rA = wm * 64 + (lane & 15);
    const int sA = lane >> 4;
    const int rB = wn * 64 + ((lane >> 4) & 1) * 8 + (lane & 7);
    const int sB = (lane >> 3) & 1;

    g2_load(sb, 0, 0, i0, j0, t); CP_COMMIT();
    g2_load(sb, 1, 1, i0, j0, t); CP_COMMIT();

    constexpr int NCH = (NT - NL) / 64;  // 96
    for (int c = 0; c < NCH; c++) {
        const int st = c % 3;
        CP_WAIT1();
        __syncthreads();
        if (c + 2 < NCH) g2_load(sb, (c + 2) % 3, c + 2, i0, j0, t);
        CP_COMMIT();
        const uint32_t bA = sb + st * 32768;
        const uint32_t bB = bA + 16384;
        #pragma unroll
        for (int kk = 0; kk < 4; kk++) {
            uint32_t af[4][4], bf[4][4];
            #pragma unroll
            for (int mt = 0; mt < 4; mt++)
                ldm_x4(af[mt], bA + smoff(rA + mt * 16, 2 * kk + sA));
            #pragma unroll
            for (int jj = 0; jj < 4; jj++)
                ldm_x4(bf[jj], bB + smoff(rB + jj * 16, 2 * kk + sB));
            #pragma unroll
            for (int mt = 0; mt < 4; mt++)
                #pragma unroll
                for (int nt = 0; nt < 8; nt++)
                    mma16816(acc[mt][nt], af[mt], &bf[nt >> 1][(nt & 1) * 2]);
        }
    }

    const int g = lane >> 2, cq = lane & 3;
    #pragma unroll
    for (int mt = 0; mt < 4; mt++) {
        #pragma unroll
        for (int h = 0; h < 2; h++) {
            const int row = i0 + wm * 64 + mt * 16 + g + h * 8;
            const float inv = 1.0f / g_rsum[row];
            float* crow = out + (size_t)row * CC;
            #pragma unroll
            for (int nt = 0; nt < 8; nt++) {
                int col = j0 + wn * 64 + nt * 8 + cq * 2;
                if (col < CC) {
                    float2 v = make_float2(acc[mt][nt][2 * h] * inv,
                                           acc[mt][nt][2 * h + 1] * inv);
                    *(float2*)(crow + col) = v;
                }
            }
        }
    }
}

// ============================================================================
// Kernel 5: scatter the labeled (one-hot) K-range into out.
// out[i][c] += (sum_{j<NL, label[j]==c} E[i][j]) / rsum[i]
// ============================================================================
__global__ __launch_bounds__(256) void scatter_kernel(float* __restrict__ out) {
    __shared__ float accum[CC];
    __shared__ int lab[NL];
    const int i = blockIdx.x, t = threadIdx.x;
    #pragma unroll
    for (int q = 0; q < 4; q++) {
        int c = t + q * 256;
        if (c < CC) accum[c] = 0.f;
    }
    #pragma unroll
    for (int q = 0; q < 8; q++) lab[t + q * 256] = g_label[t + q * 256];
    __syncthreads();
    uint4 u = ((const uint4*)(g_E + (size_t)i * NT))[t];
    const __half2* h = (const __half2*)&u;
    const int j0 = t * 8;
    #pragma unroll
    for (int k = 0; k < 4; k++) {
        float2 f = __half22float2(h[k]);
        atomicAdd(&accum[lab[j0 + 2 * k]],     f.x);
        atomicAdd(&accum[lab[j0 + 2 * k + 1]], f.y);
    }
    __syncthreads();
    const float inv = 1.0f / g_rsum[i];
    float* crow = out + (size_t)i * CC;
    #pragma unroll
    for (int q = 0; q < 4; q++) {
        int c = t + q * 256;
        if (c < CC) crow[c] += accum[c] * inv;
    }
}

// ============================================================================
// Launch. Output layout (float32):
//   [0)         anchor_feat    3145728
//   [3145728)   positive_feat  3145728
//   [6291456)   lb_feat        1048576
//   [7340032)   lb_one_hot     2048000
//   [9388032)   new_lb||new_ulb1  8192000 (contiguous 8192x1000)
//   [17580032)  logits_x_ulb_2 6144000
// ============================================================================
extern "C" void kernel_launch(void* const* d_in, const int* in_sizes, int n_in,
                              void* d_out, int out_size) {
    const float* anchor   = (const float*)d_in[0];
    const float* positive = (const float*)d_in[1];
    const float* lb_feat  = (const float*)d_in[2];
    const float* lb_oh    = (const float*)d_in[3];
    const float* lg_ulb1  = (const float*)d_in[5];
    const float* lg_ulb2  = (const float*)d_in[6];
    float* out = (float*)d_out;

    cudaMemcpyAsync(out,            anchor,   (size_t)NU * D  * sizeof(float), cudaMemcpyDeviceToDevice, 0);
    cudaMemcpyAsync(out + 3145728,  positive, (size_t)NU * D  * sizeof(float), cudaMemcpyDeviceToDevice, 0);
    cudaMemcpyAsync(out + 6291456,  lb_feat,  (size_t)NL * D  * sizeof(float), cudaMemcpyDeviceToDevice, 0);
    cudaMemcpyAsync(out + 7340032,  lb_oh,    (size_t)NL * CC * sizeof(float), cudaMemcpyDeviceToDevice, 0);
    cudaMemcpyAsync(out + 17580032, lg_ulb2,  (size_t)NU * CC * sizeof(float), cudaMemcpyDeviceToDevice, 0);

    prep_kernel<<<NT, 256>>>(lb_feat, anchor, lb_oh, lg_ulb1);
    transpose_cv_kernel<<<dim3((NT - NL) / 32, 1024 / 32), 256>>>();

    cudaFuncSetAttribute(gemm1_kernel, cudaFuncAttributeMaxDynamicSharedMemorySize, 98304);
    cudaFuncSetAttribute(gemm2_kernel, cudaFuncAttributeMaxDynamicSharedMemorySize, 98304);

    gemm1_kernel<<<NB * (NB + 1) / 2, 128, 98304>>>();   // 2080 triangular blocks
    gemm2_kernel<<<dim3(8, 64), 128, 98304>>>(out + 9388032);
    scatter_kernel<<<NT, 256>>>(out + 9388032);
}

// round 11
// speedup vs baseline: 1.0769x; 1.0325x over previous
#include <cuda_runtime.h>
#include <cuda_fp16.h>
#include <cstdint>

// Problem sizes
static constexpr int NL = 2048;
static constexpr int NU = 6144;
static constexpr int NT = 8192;   // NL + NU
static constexpr int D  = 512;
static constexpr int CC = 1000;

// Scratch (device globals; no allocation allowed)
__device__ __half g_nh[(size_t)NT * D];      // normalized feats fp16 (8MB)
__device__ float  g_cv[(size_t)NT * CC];     // class_val fp32 (rows >= NL used)
__device__ __half g_cvT[(size_t)1024 * NT];  // class_val^T fp16 (cols >= NL used)
__device__ __half g_E[(size_t)NT * NT];      // exp(S) fp16 (134MB)
__device__ float  g_rsum[NT];                // softmax denominators (atomic-accumulated)
__device__ int    g_label[NL];               // argmax of lb_one_hot rows
__device__ int    g_off[1025];               // class -> start offset in g_perm
__device__ int    g_perm[NL];                // labeled indices sorted by class

// ============================================================================
// Helpers
// ============================================================================
__device__ __forceinline__ uint32_t smem_u32(const void* p) {
    uint32_t a;
    asm("{ .reg .u64 t; cvta.to.shared.u64 t, %1; cvt.u32.u64 %0, t; }" : "=r"(a) : "l"(p));
    return a;
}
// swizzled byte offset inside a tile of 128B rows (8 x 16B segments per row)
__device__ __forceinline__ uint32_t smoff(int row, int seg) {
    return (uint32_t)(row * 128 + ((seg ^ (row & 7)) << 4));
}
#define CP16(dst, src) \
    asm volatile("cp.async.cg.shared.global [%0], [%1], 16;" :: "r"(dst), "l"(src) : "memory")
#define CP_COMMIT() asm volatile("cp.async.commit_group;" ::: "memory")
#define CP_WAIT1() asm volatile("cp.async.wait_group 1;" ::: "memory")

__device__ __forceinline__ void ldm_x4(uint32_t* r, uint32_t addr) {
    asm volatile("ldmatrix.sync.aligned.m8n8.x4.shared.b16 {%0,%1,%2,%3}, [%4];"
                 : "=r"(r[0]), "=r"(r[1]), "=r"(r[2]), "=r"(r[3]) : "r"(addr));
}
__device__ __forceinline__ void mma16816(float* d, const uint32_t* a, const uint32_t* b) {
    asm volatile(
        "mma.sync.aligned.m16n8k16.row.col.f32.f16.f16.f32 "
        "{%0,%1,%2,%3}, {%4,%5,%6,%7}, {%8,%9}, {%0,%1,%2,%3};"
        : "+f"(d[0]), "+f"(d[1]), "+f"(d[2]), "+f"(d[3])
        : "r"(a[0]), "r"(a[1]), "r"(a[2]), "r"(a[3]), "r"(b[0]), "r"(b[1]));
}

// FMA-only exp, valid for |x| <= ~11, rel err < 2e-7
__device__ __forceinline__ float fast_expf(float x) {
    float z = x * 1.4426950408889634f;
    float n = rintf(z);
    float r = fmaf(n, -0.6931471824645996f, x);
    r = fmaf(n, 1.9046542743e-9f, r);
    float p = 1.3888889225e-3f;
    p = fmaf(p, r, 8.3333337680e-3f);
    p = fmaf(p, r, 4.1666667908e-2f);
    p = fmaf(p, r, 1.6666667163e-1f);
    p = fmaf(p, r, 5.0e-1f);
    p = fmaf(p, r, 1.0f);
    p = fmaf(p, r, 1.0f);
    float s = __int_as_float(((int)n + 127) << 23);
    return p * s;
}

__device__ __forceinline__ float blockMax256(float v) {
    __shared__ float s[8];
    #pragma unroll
    for (int o = 16; o > 0; o >>= 1) v = fmaxf(v, __shfl_xor_sync(0xffffffffu, v, o));
    if ((threadIdx.x & 31) == 0) s[threadIdx.x >> 5] = v;
    __syncthreads();
    float r = s[0];
    #pragma unroll
    for (int i = 1; i < 8; i++) r = fmaxf(r, s[i]);
    __syncthreads();
    return r;
}
__device__ __forceinline__ float blockSum256(float v) {
    __shared__ float s[8];
    #pragma unroll
    for (int o = 16; o > 0; o >>= 1) v += __shfl_xor_sync(0xffffffffu, v, o);
    if ((threadIdx.x & 31) == 0) s[threadIdx.x >> 5] = v;
    __syncthreads();
    float r = s[0];
    #pragma unroll
    for (int i = 1; i < 8; i++) r += s[i];
    __syncthreads();
    return r;
}

// ============================================================================
// Kernel 1 (fused prep + pass-through copies):
//   blocks [0, NT):   normalize row -> g_nh; zero g_rsum;
//                     row < NL: extract label; else softmax(logits) -> g_cv
//   blocks [NT, NT+15168): copy 1024 floats each (the 5 pass-through outputs)
// ============================================================================
static constexpr int CPB_ANCH = 3072;   // 3145728 / 1024
static constexpr int CPB_POS  = 3072;
static constexpr int CPB_LBF  = 1024;   // 1048576 / 1024
static constexpr int CPB_OH   = 2000;   // 2048000 / 1024
static constexpr int CPB_LG2  = 6000;   // 6144000 / 1024
static constexpr int CPB_TOT  = CPB_ANCH + CPB_POS + CPB_LBF + CPB_OH + CPB_LG2; // 15168

__global__ void prep_kernel(const float* __restrict__ lb_feat,
                            const float* __restrict__ anchor,
                            const float* __restrict__ lb_one_hot,
                            const float* __restrict__ logits,
                            const float* __restrict__ positive,
                            const float* __restrict__ lg_ulb2,
                            float* __restrict__ out) {
    const int b = blockIdx.x;
    const int t = threadIdx.x;
    if (b >= NT) {
        int cb = b - NT;
        const float* src; float* dst; int blk;
        if (cb < CPB_ANCH)                       { src = anchor;   dst = out;            blk = cb; }
        else if (cb < CPB_ANCH + CPB_POS)        { src = positive; dst = out + 3145728;  blk = cb - CPB_ANCH; }
        else if (cb < CPB_ANCH + CPB_POS + CPB_LBF)
                                                 { src = lb_feat;  dst = out + 6291456;  blk = cb - CPB_ANCH - CPB_POS; }
        else if (cb < CPB_ANCH + CPB_POS + CPB_LBF + CPB_OH)
                                                 { src = lb_one_hot; dst = out + 7340032; blk = cb - CPB_ANCH - CPB_POS - CPB_LBF; }
        else                                     { src = lg_ulb2;  dst = out + 17580032; blk = cb - CPB_ANCH - CPB_POS - CPB_LBF - CPB_OH; }
        size_t o = (size_t)blk * 1024 + t * 4;
        *(float4*)(dst + o) = *(const float4*)(src + o);
        return;
    }
    const int row = b;
    // --- normalize (2 floats per thread) ---
    const float* srcn = (row < NL) ? lb_feat + (size_t)row * D
                                   : anchor + (size_t)(row - NL) * D;
    float2 v2 = ((const float2*)srcn)[t];
    float tot = blockSum256(v2.x * v2.x + v2.y * v2.y);
    float sc = 1.0f / fmaxf(sqrtf(tot), 1e-12f);
    __half2 hn = __floats2half2_rn(v2.x * sc, v2.y * sc);
    ((__half2*)(g_nh + (size_t)row * D))[t] = hn;
    if (t == 0) g_rsum[row] = 0.f;
    // --- class values / labels ---
    if (row < NL) {
        const float* src = lb_one_hot + (size_t)row * CC;
        #pragma unroll
        for (int q = 0; q < 4; q++) {
            int c = t + q * 256;
            if (c < CC && src[c] > 0.5f) g_label[row] = c;
        }
        return;
    }
    const float* src = logits + (size_t)(row - NL) * CC;
    float* dst = g_cv + (size_t)row * CC;
    float v[4];
    float mx = -1e30f;
    #pragma unroll
    for (int q = 0; q < 4; q++) {
        int j = t + q * 256;
        v[q] = (j < CC) ? src[j] : -1e30f;
        mx = fmaxf(mx, v[q]);
    }
    mx = blockMax256(mx);
    float sum = 0.f;
    #pragma unroll
    for (int q = 0; q < 4; q++) {
        int j = t + q * 256;
        float e = (j < CC) ? fast_expf(v[q] - mx) : 0.f;
        v[q] = e;
        sum += e;
    }
    sum = blockSum256(sum);
    float inv = 1.0f / sum;
    #pragma unroll
    for (int q = 0; q < 4; q++) {
        int j = t + q * 256;
        if (j < CC) dst[j] = v[q] * inv;
    }
}

// ============================================================================
// Kernel 1b: counting-sort labeled indices by class -> g_off / g_perm.
// Single block, 1024 threads. (Replaces smem-atomic scatter binning.)
// ============================================================================
__global__ void build_perm_kernel() {
    __shared__ int hist[1024];
    __shared__ int cur[1024];
    const int t = threadIdx.x;
    hist[t] = 0;
    __syncthreads();
    for (int j = t; j < NL; j += 1024) atomicAdd(&hist[g_label[j]], 1);
    __syncthreads();
    int cnt = hist[t];
    // inclusive Hillis-Steele scan (reads barrier-separated from writes)
    for (int o = 1; o < 1024; o <<= 1) {
        int other = (t >= o) ? hist[t - o] : 0;
        __syncthreads();
        hist[t] += other;
        __syncthreads();
    }
    g_off[t + 1] = hist[t];
    if (t == 0) g_off[0] = 0;
    cur[t] = hist[t] - cnt;   // exclusive offset as scatter cursor
    __syncthreads();
    for (int j = t; j < NL; j += 1024) {
        int p = atomicAdd(&cur[g_label[j]], 1);
        g_perm[p] = j;
    }
}

// ============================================================================
// Kernel 2: transpose g_cv rows [NL,NT) fp32 -> g_cvT[c][k] fp16 (k >= NL)
// ============================================================================
__global__ void transpose_cv_kernel() {
    __shared__ float s[32][33];
    const int k0 = NL + blockIdx.x * 32, c0 = blockIdx.y * 32;
    const int tx = threadIdx.x & 31, ty = threadIdx.x >> 5;
    #pragma unroll
    for (int q = 0; q < 4; q++) {
        int k = k0 + ty + q * 8, c = c0 + tx;
        s[ty + q * 8][tx] = (c < CC) ? g_cv[(size_t)k * CC + c] : 0.f;
    }
    __syncthreads();
    #pragma unroll
    for (int q = 0; q < 4; q++) {
        int c = c0 + ty + q * 8, k = k0 + tx;
        g_cvT[(size_t)c * NT + k] = __float2half_rn(s[tx][ty + q * 8]);
    }
}

// ============================================================================
// Kernel 3: GEMM1 (HMMA): dot = n@n^T (fp16); E = exp(10*dot), fused rowsums.
// SYMMETRIC triangular 128x128 blocks; off-diag also writes transposed tile.
// 4 warps (2x2), 64x64 warp tiles, 2 CTA/SM, kc=64, 3-stage (96KB).
// ============================================================================
__device__ __forceinline__ void g1_load(uint32_t sb, int s, int c, int i0, int j0, int t) {
    const uint32_t base = sb + s * 32768;
    #pragma unroll
    for (int q = 0; q < 8; q++) {
        int u = t + q * 128, row = u >> 3, seg = u & 7;
        uint32_t so = smoff(row, seg);
        size_t ga = ((size_t)(i0 + row) * D + c * 64 + seg * 8) * 2;
        size_t gb = ((size_t)(j0 + row) * D + c * 64 + seg * 8) * 2;
        CP16(base + so,         (const char*)g_nh + ga);
        CP16(base + 16384 + so, (const char*)g_nh + gb);
    }
}

static constexpr int NB = NT / 128;  // 64 blocks per dim
static constexpr int TP = 136;       // transpose-stage pitch in halves

__global__ __launch_bounds__(128, 2) void gemm1_kernel() {
    extern __shared__ char smem[];
    const uint32_t sb = smem_u32(smem);
    const int t = threadIdx.x, lane = t & 31, w = t >> 5;
    const int wm = w >> 1, wn = w & 1;           // 2 x 2 warp grid

    // triangular decode: blockIdx.x -> (bi, bj), bi <= bj
    int bi = 0, rem = blockIdx.x;
    while (rem >= NB - bi) { rem -= NB - bi; bi++; }
    const int bj = bi + rem;
    const int i0 = bi * 128, j0 = bj * 128;

    float acc[4][8][4];                           // 64 x 64 warp tile
    #pragma unroll
    for (int a = 0; a < 4; a++)
        #pragma unroll
        for (int b = 0; b < 8; b++)
            #pragma unroll
            for (int cth = 0; cth < 4; cth++) acc[a][b][cth] = 0.f;

    const int rA = wm * 64 + (lane & 15);
    const int sA = lane >> 4;
    const int rB = wn * 64 + ((lane >> 4) & 1) * 8 + (lane & 7);
    const int sB = (lane >> 3) & 1;

    g1_load(sb, 0, 0, i0, j0, t); CP_COMMIT();
    g1_load(sb, 1, 1, i0, j0, t); CP_COMMIT();

    constexpr int NCH = D / 64;  // 8 chunks
    for (int c = 0; c < NCH; c++) {
        const int st = c % 3;
        CP_WAIT1();        // retire chunk c's group
        __syncthreads();   // c visible; all reads of stage (c-1)%3 done
        if (c + 2 < NCH) g1_load(sb, (c + 2) % 3, c + 2, i0, j0, t);
        CP_COMMIT();       // always commit to keep accounting
        const uint32_t bA = sb + st * 32768;
        const uint32_t bB = bA + 16384;
        #pragma unroll
        for (int kk = 0; kk < 4; kk++) {
            uint32_t af[4][4], bf[4][4];
            #pragma unroll
            for (int mt = 0; mt < 4; mt++)
                ldm_x4(af[mt], bA + smoff(rA + mt * 16, 2 * kk + sA));
            #pragma unroll
            for (int jj = 0; jj < 4; jj++)
                ldm_x4(bf[jj], bB + smoff(rB + jj * 16, 2 * kk + sB));
            #pragma unroll
            for (int mt = 0; mt < 4; mt++)
                #pragma unroll
                for (int nt = 0; nt < 8; nt++)
                    mma16816(acc[mt][nt], af[mt], &bf[nt >> 1][(nt & 1) * 2]);
        }
    }
    __syncthreads();   // all stage reads done; smem reusable for staging

    // Epilogue: E = exp(10*acc) -> fp16; fused row sums.
    const int g = lane >> 2, cq = lane & 3;
    __half* sT = (__half*)smem;  // pitch TP halves
    #pragma unroll
    for (int mt = 0; mt < 4; mt++) {
        #pragma unroll
        for (int h = 0; h < 2; h++) {
            const int rl = wm * 64 + mt * 16 + g + h * 8;      // local row
            __half* erow = g_E + (size_t)(i0 + rl) * NT + j0 + wn * 64;
            float rs = 0.f;
            #pragma unroll
            for (int nt = 0; nt < 8; nt++) {
                float e0 = fast_expf(acc[mt][nt][2 * h] * 10.f);
                float e1 = fast_expf(acc[mt][nt][2 * h + 1] * 10.f);
                __half2 p = __floats2half2_rn(e0, e1);
                *(__half2*)(erow + nt * 8 + cq * 2) = p;
                float2 pf = __half22float2(p);   // sum the rounded values
                rs += pf.x + pf.y;
                if (bi != bj) {
                    const int cl = wn * 64 + nt * 8 + cq * 2;
                    sT[(size_t)cl * TP + rl]       = __low2half(p);
                    sT[(size_t)(cl + 1) * TP + rl] = __high2half(p);
                }
            }
            // reduce across the 4 cq lanes sharing this row
            rs += __shfl_xor_sync(0xffffffffu, rs, 1);
            rs += __shfl_xor_sync(0xffffffffu, rs, 2);
            if (cq == 0) atomicAdd(&g_rsum[i0 + rl], rs);
        }
    }
    if (bi != bj) {
        __syncthreads();
        // coalesced write of transposed tile + its row sums (= column sums)
        #pragma unroll
        for (int q = 0; q < 16; q++) {
            int u = t + q * 128;
            int row = u >> 4, seg = u & 15;  // seg == t & 15
            uint4 v = *(const uint4*)(sT + row * TP + seg * 8);
            *(uint4*)(g_E + (size_t)(j0 + row) * NT + i0 + seg * 8) = v;
            const __half2* hh = (const __half2*)&v;
            float s = 0.f;
            #pragma unroll
            for (int k = 0; k < 4; k++) {
                float2 f = __half22float2(hh[k]);
                s += f.x + f.y;
            }
            s += __shfl_xor_sync(0xffffffffu, s, 1);
            s += __shfl_xor_sync(0xffffffffu, s, 2);
            s += __shfl_xor_sync(0xffffffffu, s, 4);
            s += __shfl_xor_sync(0xffffffffu, s, 8);
            if (seg == 0) atomicAdd(&g_rsum[j0 + row], s);
        }
    }
}

// ============================================================================
// Kernel 4: GEMM2 (HMMA): out = (E[:,2048:] @ cvT[:,2048:]^T) / rsum
// Block 128x128, 4 warps (2x2), 64x64 warp tiles, 2 CTA/SM. K=6144, kc=64,
// 3-stage (96KB).
// ============================================================================
__device__ __forceinline__ void g2_load(uint32_t sb, int s, int c, int i0, int j0, int t) {
    const uint32_t base = sb + s * 32768;
    #pragma unroll
    for (int q = 0; q < 8; q++) {
        int u = t + q * 128, row = u >> 3, seg = u & 7;
        uint32_t so = smoff(row, seg);
        CP16(base + so,
             (const char*)g_E + ((size_t)(i0 + row) * NT + NL + c * 64 + seg * 8) * 2);
        CP16(base + 16384 + so,
             (const char*)g_cvT + ((size_t)(j0 + row) * NT + NL + c * 64 + seg * 8) * 2);
    }
}

__global__ __launch_bounds__(128, 2) void gemm2_kernel(float* __restrict__ out) {
    extern __shared__ char smem[];
    const uint32_t sb = smem_u32(smem);
    const int t = threadIdx.x, lane = t & 31, w = t >> 5;
    const int wm = w >> 1, wn = w & 1;           // 2 x 2 warp grid
    const int i0 = blockIdx.y * 128, j0 = blockIdx.x * 128;

    float acc[4][8][4];                           // 64 x 64 warp tile
    #pragma unroll
    for (int a = 0; a < 4; a++)
        #pragma unroll
        for (int b = 0; b < 8; b++)
            #pragma unroll
            for (int cth = 0; cth < 4; cth++) acc[a][b][cth] = 0.f;

    const int rA = wm * 64 + (lane & 15);
    const int sA = lane >> 4;
    const int rB = wn * 64 + ((lane >> 4) & 1) * 8 + (lane & 7);
    const int sB = (lane >> 3) & 1;

    g2_load(sb, 0, 0, i0, j0, t); CP_COMMIT();
    g2_load(sb, 1, 1, i0, j0, t); CP_COMMIT();

    constexpr int NCH = (NT - NL) / 64;  // 96
    for (int c = 0; c < NCH; c++) {
        const int st = c % 3;
        CP_WAIT1();
        __syncthreads();
        if (c + 2 < NCH) g2_load(sb, (c + 2) % 3, c + 2, i0, j0, t);
        CP_COMMIT();
        const uint32_t bA = sb + st * 32768;
        const uint32_t bB = bA + 16384;
        #pragma unroll
        for (int kk = 0; kk < 4; kk++) {
            uint32_t af[4][4], bf[4][4];
            #pragma unroll
            for (int mt = 0; mt < 4; mt++)
                ldm_x4(af[mt], bA + smoff(rA + mt * 16, 2 * kk + sA));
            #pragma unroll
            for (int jj = 0; jj < 4; jj++)
                ldm_x4(bf[jj], bB + smoff(rB + jj * 16, 2 * kk + sB));
            #pragma unroll
            for (int mt = 0; mt < 4; mt++)
                #pragma unroll
                for (int nt = 0; nt < 8; nt++)
                    mma16816(acc[mt][nt], af[mt], &bf[nt >> 1][(nt & 1) * 2]);
        }
    }

    const int g = lane >> 2, cq = lane & 3;
    #pragma unroll
    for (int mt = 0; mt < 4; mt++) {
        #pragma unroll
        for (int h = 0; h < 2; h++) {
            const int row = i0 + wm * 64 + mt * 16 + g + h * 8;
            const float inv = 1.0f / g_rsum[row];
            float* crow = out + (size_t)row * CC;
            #pragma unroll
            for (int nt = 0; nt < 8; nt++) {
                int col = j0 + wn * 64 + nt * 8 + cq * 2;
                if (col < CC) {
                    float2 v = make_float2(acc[mt][nt][2 * h] * inv,
                                           acc[mt][nt][2 * h + 1] * inv);
                    *(float2*)(crow + col) = v;
                }
            }
        }
    }
}

// ============================================================================
// Kernel 5: scatter the labeled (one-hot) K-range into out — ATOMIC-FREE.
// out[i][c] += (sum over sorted class segment of E[i][perm[k]]) / rsum[i]
// ============================================================================
__global__ __launch_bounds__(256) void scatter_kernel(float* __restrict__ out) {
    __shared__ __half Es[NL];       // 4 KB: staged E row (labeled columns)
    __shared__ int perm_s[NL];      // 8 KB
    __shared__ int off_s[1001];     // 4 KB
    const int i = blockIdx.x, t = threadIdx.x;
    ((uint4*)Es)[t] = ((const uint4*)(g_E + (size_t)i * NT))[t];  // 2048 halves
    #pragma unroll
    for (int q = 0; q < 8; q++) perm_s[t + q * 256] = g_perm[t + q * 256];
    #pragma unroll
    for (int q = 0; q < 4; q++) {
        int c = t + q * 256;
        if (c <= CC) off_s[c] = g_off[c];
    }
    __syncthreads();
    const float inv = 1.0f / g_rsum[i];
    float* crow = out + (size_t)i * CC;
    #pragma unroll
    for (int q = 0; q < 4; q++) {
        int c = t + q * 256;
        if (c < CC) {
            int b = off_s[c], e = off_s[c + 1];
            float s = 0.f;
            for (int k = b; k < e; k++) s += __half2float(Es[perm_s[k]]);
            crow[c] += s * inv;
        }
    }
}

// ============================================================================
// Launch. Output layout (float32):
//   [0)         anchor_feat    3145728
//   [3145728)   positive_feat  3145728
//   [6291456)   lb_feat        1048576
//   [7340032)   lb_one_hot     2048000
//   [9388032)   new_lb||new_ulb1  8192000 (contiguous 8192x1000)
//   [17580032)  logits_x_ulb_2 6144000
// ============================================================================
extern "C" void kernel_launch(void* const* d_in, const int* in_sizes, int n_in,
                              void* d_out, int out_size) {
    const float* anchor   = (const float*)d_in[0];
    const float* positive = (const float*)d_in[1];
    const float* lb_feat  = (const float*)d_in[2];
    const float* lb_oh    = (const float*)d_in[3];
    const float* lg_ulb1  = (const float*)d_in[5];
    const float* lg_ulb2  = (const float*)d_in[6];
    float* out = (float*)d_out;

    prep_kernel<<<NT + CPB_TOT, 256>>>(lb_feat, anchor, lb_oh, lg_ulb1,
                                       positive, lg_ulb2, out);
    build_perm_kernel<<<1, 1024>>>();
    transpose_cv_kernel<<<dim3((NT - NL) / 32, 1024 / 32), 256>>>();

    cudaFuncSetAttribute(gemm1_kernel, cudaFuncAttributeMaxDynamicSharedMemorySize, 98304);
    cudaFuncSetAttribute(gemm2_kernel, cudaFuncAttributeMaxDynamicSharedMemorySize, 98304);

    gemm1_kernel<<<NB * (NB + 1) / 2, 128, 98304>>>();   // 2080 triangular blocks
    gemm2_kernel<<<dim3(8, 64), 128, 98304>>>(out + 9388032);
    scatter_kernel<<<NT, 256>>>(out + 9388032);
}